// round 8
// baseline (speedup 1.0000x reference)
#include <cuda_runtime.h>
#include <math.h>

#define NPERROW (512*512)            // 262144
#define NROWS   128
#define NV4     (NPERROW/4)          // 65536
#define FULLM   0xFFFFFFFFu

// ---- gather / gate shape ----
#define CHUNKS  16
#define GTH     256
#define V4C     (NV4/CHUNKS)         // 4096 float4 per chunk
#define V4T     (V4C/GTH)            // 16 float4 per thread
#define GWARPS  (GTH/32)             // 8
#define TCAP    24                   // per-thread stage cap (exp 2.9, ~11 sigma)
#define CSEG    1024                 // per-chunk global segment cap (exp ~746)

// ---- selection ----
#define NTHREADS 1024
#define NBINS   16384                // top-14-bit histogram
#define BPT     (NBINS/NTHREADS)     // 16
#define MCAP    (CHUNKS*CSEG)        // 16384
#define CCAP    4096                 // candidate buffer per side
#define SMEM_WORDS (NBINS + MCAP + 2*CCAP)   // 40960
#define SMEM_BYTES (SMEM_WORDS*4)            // 163840

__device__ unsigned int g_buf[NROWS][CHUNKS*CSEG];   // 8 MB scratch
__device__ unsigned int g_ccnt[NROWS][CHUNKS];       // per-chunk counts (0xFFFFFFFF = overflow)
__device__ float g_scale[NROWS];
__device__ float g_t[NROWS];

// monotone float -> uint key
__device__ __forceinline__ unsigned int f2k(float f) {
    unsigned int u = __float_as_uint(f);
    return u ^ ((unsigned int)((int)u >> 31) | 0x80000000u);
}
__device__ __forceinline__ float k2f(unsigned int k) {
    unsigned int u = (k & 0x80000000u) ? (k ^ 0x80000000u) : ~k;
    return __uint_as_float(u);
}
__device__ __forceinline__ float ex2a(float x){ float r; asm("ex2.approx.ftz.f32 %0, %1;" : "=f"(r) : "f"(x)); return r; }
__device__ __forceinline__ float rcpa(float x){ float r; asm("rcp.approx.ftz.f32 %0, %1;" : "=f"(r) : "f"(x)); return r; }

// ===================== Kernel 1: wide tail gather (MLP-batched) =====================
__global__ __launch_bounds__(GTH)
void gather_kernel(const float* __restrict__ x)
{
    __shared__ unsigned int stage[TCAP * GTH];   // per-thread stripes, conflict-free
    __shared__ unsigned int wsum[GWARPS];
    __shared__ int s_ov;

    const int tid  = threadIdx.x;
    const int lane = tid & 31;
    const int wid  = tid >> 5;
    const int row  = blockIdx.x >> 4;
    const int chk  = blockIdx.x & (CHUNKS - 1);
    const float4* xr = (const float4*)(x + (size_t)row * NPERROW) + (size_t)chk * V4C;

    if (tid == 0) s_ov = 0;
    __syncthreads();

    unsigned int cnt = 0;
    #pragma unroll
    for (int it = 0; it < V4T / 4; it++) {
        // batch 4 independent 128-bit loads (MLP >= 4) before the branchy filter
        float4 v0 = __ldcs(&xr[tid + (it * 4 + 0) * GTH]);
        float4 v1 = __ldcs(&xr[tid + (it * 4 + 1) * GTH]);
        float4 v2 = __ldcs(&xr[tid + (it * 4 + 2) * GTH]);
        float4 v3 = __ldcs(&xr[tid + (it * 4 + 3) * GTH]);
        float f[16] = {v0.x, v0.y, v0.z, v0.w, v1.x, v1.y, v1.z, v1.w,
                       v2.x, v2.y, v2.z, v2.w, v3.x, v3.y, v3.z, v3.w};
        #pragma unroll
        for (int e = 0; e < 16; e++) {
            if (fabsf(f[e]) > 2.0f) {
                if (cnt < TCAP) stage[cnt * GTH + tid] = f2k(f[e]);
                cnt++;
            }
        }
    }
    if (cnt > TCAP) s_ov = 1;   // benign race; ordered by barriers below

    // block exclusive scan of per-thread counts
    unsigned int inc = cnt;
    #pragma unroll
    for (int o = 1; o < 32; o <<= 1) {
        unsigned int t = __shfl_up_sync(FULLM, inc, o);
        if (lane >= o) inc += t;
    }
    if (lane == 31) wsum[wid] = inc;
    __syncthreads();
    if (tid < GWARPS) {
        unsigned int w = wsum[tid];
        #pragma unroll
        for (int o = 1; o < GWARPS; o <<= 1) {
            unsigned int t = __shfl_up_sync(0xFFu, w, o);
            if (tid >= o) w += t;
        }
        wsum[tid] = w;
    }
    __syncthreads();

    unsigned int pre   = (wid ? wsum[wid - 1] : 0u) + inc - cnt;
    unsigned int total = wsum[GWARPS - 1];
    int ov = s_ov || (total > CSEG);

    if (!ov) {
        unsigned int* dst = &g_buf[row][chk * CSEG + pre];
        for (unsigned int j = 0; j < cnt; j++) dst[j] = stage[j * GTH + tid];
    }
    if (tid == 0) g_ccnt[row][chk] = ov ? 0xFFFFFFFFu : total;
}

// ===================== Kernel 2: per-row selection =====================
extern __shared__ unsigned int smem_u[];

__global__ __launch_bounds__(NTHREADS, 1)
void select_kernel(const float* __restrict__ x,
                   const float* __restrict__ alpha_p,
                   const float* __restrict__ beta_p)
{
    unsigned int* hist  = smem_u;            // NBINS
    unsigned int* mix   = hist + NBINS;      // MCAP
    unsigned int* candL = mix + MCAP;        // CCAP
    unsigned int* candH = candL + CCAP;      // CCAP

    __shared__ unsigned int wsum[32];
    __shared__ unsigned int cpre[CHUNKS + 1];
    __shared__ unsigned int s_M, cntL, cntH;
    __shared__ int          s_bad;
    __shared__ int          binOf[4];
    __shared__ unsigned int preOf[4];
    __shared__ float        s_v[4];

    const int tid  = threadIdx.x;
    const int lane = tid & 31;
    const int wid  = tid >> 5;
    const int row  = blockIdx.x;
    const float4* xr = (const float4*)(x + (size_t)row * NPERROW);

    if (tid == 0) {
        unsigned int t = 0; int bad = 0;
        #pragma unroll
        for (int c = 0; c < CHUNKS; c++) {
            unsigned int cc = g_ccnt[row][c];
            if (cc > CSEG) { bad = 1; cc = 0; }
            cpre[c] = t;
            t += cc;
        }
        cpre[CHUNKS] = t;
        if (t < 5246u) bad = 1;   // both tails need >= 2623 elements
        s_M = t; s_bad = bad;
        cntL = 0u; cntH = 0u;
    }
    __syncthreads();

    const unsigned int M = s_M;
    int mode = s_bad ? 1 : 0;   // 0 = gathered tail set, 1 = exact full-row fallback

    if (mode == 0) {
        #pragma unroll
        for (int c = 0; c < CHUNKS; c++) {
            unsigned int cnt = cpre[c + 1] - cpre[c];   // <= CSEG = NTHREADS
            if ((unsigned int)tid < cnt) mix[cpre[c] + tid] = g_buf[row][c * CSEG + tid];
        }
    }
    __syncthreads();

    const unsigned int BL2 = f2k(-2.0f) >> 18;
    const unsigned int BH2 = f2k( 2.0f) >> 18;
    unsigned int R[4];

    // ---------------- L1: 14-bit histogram + inline rank locate ----------------
    for (;;) {
        if (mode == 0) { R[0] = 2621u; R[1] = 2622u; R[2] = M - 2623u; R[3] = M - 2622u; }
        else           { R[0] = 2621u; R[1] = 2622u; R[2] = 259521u;   R[3] = 259522u;  }

        #pragma unroll
        for (int j = 0; j < BPT; j++) hist[tid + j * NTHREADS] = 0u;
        __syncthreads();

        if (mode == 0) {
            for (unsigned int i = tid; i < M; i += NTHREADS)
                atomicAdd(&hist[mix[i] >> 18], 1u);
        } else {
            for (int i = tid; i < NV4; i += NTHREADS) {
                float4 v = xr[i];
                atomicAdd(&hist[f2k(v.x) >> 18], 1u);
                atomicAdd(&hist[f2k(v.y) >> 18], 1u);
                atomicAdd(&hist[f2k(v.z) >> 18], 1u);
                atomicAdd(&hist[f2k(v.w) >> 18], 1u);
            }
        }
        __syncthreads();

        // shfl-based block scan over 16384 bins + inline locate
        unsigned int loc[BPT];
        unsigned int s = 0;
        #pragma unroll
        for (int j = 0; j < BPT; j++) { loc[j] = hist[tid * BPT + j]; s += loc[j]; }
        unsigned int inc = s;
        #pragma unroll
        for (int o = 1; o < 32; o <<= 1) {
            unsigned int t = __shfl_up_sync(FULLM, inc, o);
            if (lane >= o) inc += t;
        }
        if (lane == 31) wsum[wid] = inc;
        __syncthreads();
        if (tid < 32) {
            unsigned int w = wsum[tid];
            #pragma unroll
            for (int o = 1; o < 32; o <<= 1) {
                unsigned int t = __shfl_up_sync(FULLM, w, o);
                if (lane >= o) w += t;
            }
            wsum[tid] = w;
        }
        __syncthreads();
        unsigned int run = (wid ? wsum[wid - 1] : 0u) + inc - s;
        #pragma unroll
        for (int j = 0; j < BPT; j++) {
            unsigned int c = loc[j];
            int b = tid * BPT + j;
            #pragma unroll
            for (int q = 0; q < 4; q++)
                if (run <= R[q] && R[q] < run + c) { binOf[q] = b; preOf[q] = run; }
            run += c;
        }
        __syncthreads();

        if (mode == 0) {
            if (binOf[1] > (int)BL2 || binOf[2] < (int)BH2) { mode = 1; __syncthreads(); continue; }
        }
        break;
    }

    // -------- extract candidates for both sides (plain smem atomics; tiny counts) --------
    const unsigned int kminL = (unsigned int)binOf[0] << 18;
    const unsigned int kmaxL = (((unsigned int)(binOf[1] + 1)) << 18) - 1u;
    const unsigned int kminH = (unsigned int)binOf[2] << 18;
    const unsigned int kmaxH = (((unsigned int)(binOf[3] + 1)) << 18) - 1u;

    if (mode == 0) {
        for (unsigned int i = tid; i < M; i += NTHREADS) {
            unsigned int k = mix[i];
            if (k >= kminL && k <= kmaxL) { unsigned int p = atomicAdd(&cntL, 1u); if (p < CCAP) candL[p] = k; }
            if (k >= kminH && k <= kmaxH) { unsigned int p = atomicAdd(&cntH, 1u); if (p < CCAP) candH[p] = k; }
        }
    } else {
        for (int i = tid; i < NV4; i += NTHREADS) {
            float4 v = xr[i];
            unsigned int ks[4] = {f2k(v.x), f2k(v.y), f2k(v.z), f2k(v.w)};
            #pragma unroll
            for (int e = 0; e < 4; e++) {
                unsigned int k = ks[e];
                if (k >= kminL && k <= kmaxL) { unsigned int p = atomicAdd(&cntL, 1u); if (p < CCAP) candL[p] = k; }
                if (k >= kminH && k <= kmaxH) { unsigned int p = atomicAdd(&cntH, 1u); if (p < CCAP) candH[p] = k; }
            }
        }
    }
    __syncthreads();

    // -------- rank-by-count selection (exact, handles duplicates) --------
    #pragma unroll
    for (int side = 0; side < 2; side++) {
        unsigned int* cand = side ? candH : candL;
        unsigned int  n    = min(side ? cntH : cntL, (unsigned int)CCAP);
        unsigned int  lr0  = R[side * 2]     - preOf[side * 2];
        unsigned int  lr1  = R[side * 2 + 1] - preOf[side * 2];

        for (unsigned int j = tid; j < n; j += NTHREADS) {
            unsigned int kj = cand[j];
            unsigned int c = 0;
            for (unsigned int i = 0; i < n; i++) {
                unsigned int ki = cand[i];           // broadcast read
                c += (ki < kj) || (ki == kj && i < j);
            }
            if (c == lr0) s_v[side * 2]     = k2f(kj);
            if (c == lr1) s_v[side * 2 + 1] = k2f(kj);
        }
    }
    __syncthreads();

    // ---------------- threshold ----------------
    if (tid == 0) {
        double posLo  = 0.01 * (double)(NPERROW - 1);
        double posHi  = 0.99 * (double)(NPERROW - 1);
        double fracLo = posLo - 2621.0;
        double fracHi = posHi - 259521.0;

        double i1  = (double)s_v[0] + fracLo * ((double)s_v[1] - (double)s_v[0]);
        double i99 = (double)s_v[2] + fracHi * ((double)s_v[3] - (double)s_v[2]);

        float alpha = alpha_p[0];
        float beta  = beta_p[0];
        float th = (float)(i1 + (i99 - i1) * (double)alpha);
        float mask   = (th > 1e-14f) ? 1.0f : 0.0f;
        float th_new = th * mask + (1.0f - mask);
        g_scale[row] = beta / th_new;
        g_t[row]     = th * mask;
    }
}

// ===================== Kernel 3: streaming gate =====================
__global__ __launch_bounds__(GTH)
void gate_kernel(const float* __restrict__ x, float* __restrict__ out)
{
    const int c   = blockIdx.x;
    const int row = c >> 4;            // CHUNKS = 16
    const int chk = c & 15;
    const float4* xr   = (const float4*)(x   + (size_t)row * NPERROW) + (size_t)chk * V4C;
    float4*       outr = (float4*)      (out + (size_t)row * NPERROW) + (size_t)chk * V4C;

    const float scale = g_scale[row];
    const float t     = g_t[row];
    const float L2E   = 1.4426950408889634f;
    const float a = scale * L2E;        // exp(-(scale*(|x|-t))) = 2^(-a*|x| + b)
    const float b = scale * t * L2E;

    #pragma unroll 4
    for (int i = threadIdx.x; i < V4C; i += GTH) {
        float4 v = __ldcs(&xr[i]);
        float4 o;
        o.x = fmaxf(v.x, 0.0f) * rcpa(1.0f + ex2a(fmaf(fabsf(v.x), -a, b)));
        o.y = fmaxf(v.y, 0.0f) * rcpa(1.0f + ex2a(fmaf(fabsf(v.y), -a, b)));
        o.z = fmaxf(v.z, 0.0f) * rcpa(1.0f + ex2a(fmaf(fabsf(v.z), -a, b)));
        o.w = fmaxf(v.w, 0.0f) * rcpa(1.0f + ex2a(fmaf(fabsf(v.w), -a, b)));
        __stcs(&outr[i], o);
    }
}

extern "C" void kernel_launch(void* const* d_in, const int* in_sizes, int n_in,
                              void* d_out, int out_size)
{
    const float* x     = (const float*)d_in[0];
    const float* alpha = (const float*)d_in[1];
    const float* beta  = (const float*)d_in[2];
    float* out = (float*)d_out;

    cudaFuncSetAttribute(select_kernel, cudaFuncAttributeMaxDynamicSharedMemorySize, SMEM_BYTES);

    gather_kernel<<<NROWS * CHUNKS, GTH>>>(x);
    select_kernel<<<NROWS, NTHREADS, SMEM_BYTES>>>(x, alpha, beta);
    gate_kernel<<<NROWS * CHUNKS, GTH>>>(x, out);
}